// round 4
// baseline (speedup 1.0000x reference)
#include <cuda_runtime.h>

// Problem constants (from reference: N=100000, DIM=128, HEADS=4, C=32, E=1600000)
#define NMAX 100000
#define DIMK 128

// Scratch (static __device__ arrays — allocation-free per harness rules)
__device__ float g_xp[NMAX * DIMK];      // x @ W, [N,128]    (51.2 MB)
__device__ float g_asrc[NMAX * 4];       // [N,H]
__device__ float g_adst[NMAX * 4];       // [N,H]
__device__ float g_s[NMAX * 4];          // softmax denominators [N,H]

// ---------------------------------------------------------------------------
// Kernel 1: x_proj = x @ W   (fp32 SIMT GEMM, 64-row tiles)
// block: 256 threads = 8 warps; warp w computes rows [64*bx + 8w .. +7], all 128 cols
// thread: 8 rows x 4 cols accumulators; W row read as float4 (L1-resident, 64KB)
// ---------------------------------------------------------------------------
__global__ void __launch_bounds__(256) gemm_kernel(const float* __restrict__ x,
                                                   const float* __restrict__ W, int N) {
    __shared__ float sx[64][DIMK];
    const int block_row = blockIdx.x * 64;
    const int tid = threadIdx.x;
    const int nrows = min(64, N - block_row);

    // load x tile (coalesced float4)
    const float4* x4 = (const float4*)(x + (size_t)block_row * DIMK);
    float4* sx4 = (float4*)&sx[0][0];
    for (int i = tid; i < nrows * 32; i += 256) sx4[i] = x4[i];
    __syncthreads();

    const int cg = tid & 31;   // col group: cols 4*cg .. 4*cg+3
    const int rg = tid >> 5;   // warp id: rows rg*8 .. rg*8+7

    float4 acc[8];
#pragma unroll
    for (int i = 0; i < 8; i++) acc[i] = make_float4(0.f, 0.f, 0.f, 0.f);

    const float4* W4 = (const float4*)W;
#pragma unroll 4
    for (int k = 0; k < DIMK; k++) {
        const float4 w = __ldg(&W4[k * 32 + cg]);
#pragma unroll
        for (int i = 0; i < 8; i++) {
            const float xv = sx[rg * 8 + i][k];
            acc[i].x = fmaf(xv, w.x, acc[i].x);
            acc[i].y = fmaf(xv, w.y, acc[i].y);
            acc[i].z = fmaf(xv, w.z, acc[i].z);
            acc[i].w = fmaf(xv, w.w, acc[i].w);
        }
    }
    float4* xp4 = (float4*)g_xp;
#pragma unroll
    for (int i = 0; i < 8; i++) {
        const int row = block_row + rg * 8 + i;
        if (row < N) xp4[row * 32 + cg] = acc[i];
    }
}

// ---------------------------------------------------------------------------
// Kernel 2: per-node attention coefficients a_src/a_dst; also zero s and out.
// one warp per node; lane l handles channels 4l..4l+3 (head l>>3).
// ---------------------------------------------------------------------------
__global__ void __launch_bounds__(256) a_kernel(const float* __restrict__ att_src,
                                                const float* __restrict__ att_dst,
                                                float* __restrict__ out, int N) {
    const int warp = (blockIdx.x * blockDim.x + threadIdx.x) >> 5;
    const int lane = threadIdx.x & 31;
    if (warp >= N) return;

    const float4 xv = ((const float4*)g_xp)[warp * 32 + lane];
    // att flattened [H,C] row-major: global col 4*lane == h*32 + c => index = lane (float4)
    const float4 as = __ldg(&((const float4*)att_src)[lane]);
    const float4 ad = __ldg(&((const float4*)att_dst)[lane]);

    float ps = xv.x * as.x + xv.y * as.y + xv.z * as.z + xv.w * as.w;
    float pd = xv.x * ad.x + xv.y * ad.y + xv.z * ad.z + xv.w * ad.w;
    // reduce within each 8-lane head group
#pragma unroll
    for (int off = 4; off >= 1; off >>= 1) {
        ps += __shfl_xor_sync(0xffffffffu, ps, off);
        pd += __shfl_xor_sync(0xffffffffu, pd, off);
    }
    if ((lane & 7) == 0) {
        const int h = lane >> 3;
        g_asrc[warp * 4 + h] = ps;
        g_adst[warp * 4 + h] = pd;
        g_s[warp * 4 + h] = 0.f;
    }
    ((float4*)out)[warp * 32 + lane] = make_float4(0.f, 0.f, 0.f, 0.f);
}

// ---------------------------------------------------------------------------
// Kernel 3: edge scatter. One warp per edge (incl. N virtual self-loop edges).
// Max-shift in softmax cancels => accumulate unnormalized exp(alpha)*x_proj[src]
// into out[dst] and exp-sums into s[dst]. Vector red.v4.f32 (4x fewer atomics).
// NOTE: edge_index arrives as int32 (JAX x64 disabled coerces int64 -> int32).
// ---------------------------------------------------------------------------
__global__ void __launch_bounds__(256) edge_kernel(const int* __restrict__ ei,
                                                   float* __restrict__ out,
                                                   int E, int E2) {
    const int warp = (blockIdx.x * blockDim.x + threadIdx.x) >> 5;
    const int lane = threadIdx.x & 31;
    if (warp >= E2) return;

    int src, dst;
    if (warp < E) {
        src = ei[warp];       // edge_index[0][e]
        dst = ei[E + warp];   // edge_index[1][e]
    } else {
        src = dst = warp - E; // self loop
    }

    float myex = 0.f;
    if (lane < 4) {
        float a = g_asrc[src * 4 + lane] + g_adst[dst * 4 + lane];
        a = (a >= 0.f) ? a : 0.2f * a;           // leaky relu, slope 0.2
        myex = __expf(a);
        atomicAdd(&g_s[dst * 4 + lane], myex);
    }
    const float exh = __shfl_sync(0xffffffffu, myex, lane >> 3);

    const float4 xv = ((const float4*)g_xp)[src * 32 + lane];
    float* p = out + (size_t)dst * DIMK + lane * 4;
    asm volatile("red.global.add.v4.f32 [%0], {%1,%2,%3,%4};"
                 :: "l"(p), "f"(exh * xv.x), "f"(exh * xv.y),
                    "f"(exh * xv.z), "f"(exh * xv.w)
                 : "memory");
}

// ---------------------------------------------------------------------------
// Kernel 4: out = relu(out / (s + 1e-16) + bias)
// ---------------------------------------------------------------------------
__global__ void __launch_bounds__(256) norm_kernel(const float* __restrict__ bias,
                                                   float* __restrict__ out, int N) {
    const int i = blockIdx.x * blockDim.x + threadIdx.x;  // over N*32 float4s
    if (i >= N * 32) return;
    const int node = i >> 5;
    const int lane = i & 31;
    const int h = lane >> 3;
    const float inv = 1.f / (g_s[node * 4 + h] + 1e-16f);
    float4 v = ((float4*)out)[i];
    const float4 b = __ldg(&((const float4*)bias)[lane]);
    v.x = fmaxf(fmaf(v.x, inv, b.x), 0.f);
    v.y = fmaxf(fmaf(v.y, inv, b.y), 0.f);
    v.z = fmaxf(fmaf(v.z, inv, b.z), 0.f);
    v.w = fmaxf(fmaf(v.w, inv, b.w), 0.f);
    ((float4*)out)[i] = v;
}

// ---------------------------------------------------------------------------
extern "C" void kernel_launch(void* const* d_in, const int* in_sizes, int n_in,
                              void* d_out, int out_size) {
    const float* x        = (const float*)d_in[0];
    const int* ei         = (const int*)d_in[1];   // int32! (JAX x64 disabled)
    const float* W        = (const float*)d_in[2];
    const float* att_src  = (const float*)d_in[3];
    const float* att_dst  = (const float*)d_in[4];
    const float* bias     = (const float*)d_in[5];
    float* out            = (float*)d_out;

    const int N  = in_sizes[0] / DIMK;
    const int E  = in_sizes[1] / 2;
    const int E2 = E + N;   // with self loops

    gemm_kernel<<<(N + 63) / 64, 256>>>(x, W, N);
    a_kernel<<<(N * 32 + 255) / 256, 256>>>(att_src, att_dst, out, N);
    edge_kernel<<<(E2 + 7) / 8, 256>>>(ei, out, E, E2);
    norm_kernel<<<(N * 32 + 255) / 256, 256>>>(bias, out, N);
}

// round 5
// speedup vs baseline: 1.0017x; 1.0017x over previous
#include <cuda_runtime.h>

// Problem constants (from reference: N=100000, DIM=128, HEADS=4, C=32, E=1600000)
#define NMAX 100000
#define DIMK 128

// Scratch (static __device__ arrays — allocation-free per harness rules)
__device__ float g_xp[NMAX * DIMK];      // x @ W, [N,128]    (51.2 MB)
__device__ float g_asrc[NMAX * 4];       // [N,H]
__device__ float g_adst[NMAX * 4];       // [N,H]
__device__ float g_s[NMAX * 4];          // softmax denominators [N,H]

// ---------------------------------------------------------------------------
// Kernel 1: x_proj = x @ W   (fp32 SIMT GEMM, 64-row tiles)
// block: 256 threads = 8 warps; warp w computes rows [64*bx + 8w .. +7], all 128 cols
// thread: 8 rows x 4 cols accumulators; W row read as float4 (L1-resident, 64KB)
// ---------------------------------------------------------------------------
__global__ void __launch_bounds__(256) gemm_kernel(const float* __restrict__ x,
                                                   const float* __restrict__ W, int N) {
    __shared__ float sx[64][DIMK];
    const int block_row = blockIdx.x * 64;
    const int tid = threadIdx.x;
    const int nrows = min(64, N - block_row);

    // load x tile (coalesced float4)
    const float4* x4 = (const float4*)(x + (size_t)block_row * DIMK);
    float4* sx4 = (float4*)&sx[0][0];
    for (int i = tid; i < nrows * 32; i += 256) sx4[i] = x4[i];
    __syncthreads();

    const int cg = tid & 31;   // col group: cols 4*cg .. 4*cg+3
    const int rg = tid >> 5;   // warp id: rows rg*8 .. rg*8+7

    float4 acc[8];
#pragma unroll
    for (int i = 0; i < 8; i++) acc[i] = make_float4(0.f, 0.f, 0.f, 0.f);

    const float4* W4 = (const float4*)W;
#pragma unroll 4
    for (int k = 0; k < DIMK; k++) {
        const float4 w = __ldg(&W4[k * 32 + cg]);
#pragma unroll
        for (int i = 0; i < 8; i++) {
            const float xv = sx[rg * 8 + i][k];
            acc[i].x = fmaf(xv, w.x, acc[i].x);
            acc[i].y = fmaf(xv, w.y, acc[i].y);
            acc[i].z = fmaf(xv, w.z, acc[i].z);
            acc[i].w = fmaf(xv, w.w, acc[i].w);
        }
    }
    float4* xp4 = (float4*)g_xp;
#pragma unroll
    for (int i = 0; i < 8; i++) {
        const int row = block_row + rg * 8 + i;
        if (row < N) xp4[row * 32 + cg] = acc[i];
    }
}

// ---------------------------------------------------------------------------
// Kernel 2: per-node attention coefficients a_src/a_dst; also zero s and out.
// one warp per node; lane l handles channels 4l..4l+3 (head l>>3).
// ---------------------------------------------------------------------------
__global__ void __launch_bounds__(256) a_kernel(const float* __restrict__ att_src,
                                                const float* __restrict__ att_dst,
                                                float* __restrict__ out, int N) {
    const int warp = (blockIdx.x * blockDim.x + threadIdx.x) >> 5;
    const int lane = threadIdx.x & 31;
    if (warp >= N) return;

    const float4 xv = ((const float4*)g_xp)[warp * 32 + lane];
    // att flattened [H,C] row-major: global col 4*lane == h*32 + c => index = lane (float4)
    const float4 as = __ldg(&((const float4*)att_src)[lane]);
    const float4 ad = __ldg(&((const float4*)att_dst)[lane]);

    float ps = xv.x * as.x + xv.y * as.y + xv.z * as.z + xv.w * as.w;
    float pd = xv.x * ad.x + xv.y * ad.y + xv.z * ad.z + xv.w * ad.w;
    // reduce within each 8-lane head group
#pragma unroll
    for (int off = 4; off >= 1; off >>= 1) {
        ps += __shfl_xor_sync(0xffffffffu, ps, off);
        pd += __shfl_xor_sync(0xffffffffu, pd, off);
    }
    if ((lane & 7) == 0) {
        const int h = lane >> 3;
        g_asrc[warp * 4 + h] = ps;
        g_adst[warp * 4 + h] = pd;
        g_s[warp * 4 + h] = 0.f;
    }
    ((float4*)out)[warp * 32 + lane] = make_float4(0.f, 0.f, 0.f, 0.f);
}

// ---------------------------------------------------------------------------
// Kernel 3: edge scatter. One warp per edge (incl. N virtual self-loop edges).
// Max-shift in softmax cancels => accumulate unnormalized exp(alpha)*x_proj[src]
// into out[dst] and exp-sums into s[dst]. Vector red.v4.f32 (4x fewer atomics).
// NOTE: edge_index arrives as int32 (JAX x64 disabled coerces int64 -> int32).
// ---------------------------------------------------------------------------
__global__ void __launch_bounds__(256) edge_kernel(const int* __restrict__ ei,
                                                   float* __restrict__ out,
                                                   int E, int E2) {
    const int warp = (blockIdx.x * blockDim.x + threadIdx.x) >> 5;
    const int lane = threadIdx.x & 31;
    if (warp >= E2) return;

    int src, dst;
    if (warp < E) {
        src = ei[warp];       // edge_index[0][e]
        dst = ei[E + warp];   // edge_index[1][e]
    } else {
        src = dst = warp - E; // self loop
    }

    float myex = 0.f;
    if (lane < 4) {
        float a = g_asrc[src * 4 + lane] + g_adst[dst * 4 + lane];
        a = (a >= 0.f) ? a : 0.2f * a;           // leaky relu, slope 0.2
        myex = __expf(a);
        atomicAdd(&g_s[dst * 4 + lane], myex);
    }
    const float exh = __shfl_sync(0xffffffffu, myex, lane >> 3);

    const float4 xv = ((const float4*)g_xp)[src * 32 + lane];
    float* p = out + (size_t)dst * DIMK + lane * 4;
    asm volatile("red.global.add.v4.f32 [%0], {%1,%2,%3,%4};"
                 :: "l"(p), "f"(exh * xv.x), "f"(exh * xv.y),
                    "f"(exh * xv.z), "f"(exh * xv.w)
                 : "memory");
}

// ---------------------------------------------------------------------------
// Kernel 4: out = relu(out / (s + 1e-16) + bias)
// ---------------------------------------------------------------------------
__global__ void __launch_bounds__(256) norm_kernel(const float* __restrict__ bias,
                                                   float* __restrict__ out, int N) {
    const int i = blockIdx.x * blockDim.x + threadIdx.x;  // over N*32 float4s
    if (i >= N * 32) return;
    const int node = i >> 5;
    const int lane = i & 31;
    const int h = lane >> 3;
    const float inv = 1.f / (g_s[node * 4 + h] + 1e-16f);
    float4 v = ((float4*)out)[i];
    const float4 b = __ldg(&((const float4*)bias)[lane]);
    v.x = fmaxf(fmaf(v.x, inv, b.x), 0.f);
    v.y = fmaxf(fmaf(v.y, inv, b.y), 0.f);
    v.z = fmaxf(fmaf(v.z, inv, b.z), 0.f);
    v.w = fmaxf(fmaf(v.w, inv, b.w), 0.f);
    ((float4*)out)[i] = v;
}

// ---------------------------------------------------------------------------
extern "C" void kernel_launch(void* const* d_in, const int* in_sizes, int n_in,
                              void* d_out, int out_size) {
    const float* x        = (const float*)d_in[0];
    const int* ei         = (const int*)d_in[1];   // int32! (JAX x64 disabled)
    const float* W        = (const float*)d_in[2];
    const float* att_src  = (const float*)d_in[3];
    const float* att_dst  = (const float*)d_in[4];
    const float* bias     = (const float*)d_in[5];
    float* out            = (float*)d_out;

    const int N  = in_sizes[0] / DIMK;
    const int E  = in_sizes[1] / 2;
    const int E2 = E + N;   // with self loops

    gemm_kernel<<<(N + 63) / 64, 256>>>(x, W, N);
    a_kernel<<<(N * 32 + 255) / 256, 256>>>(att_src, att_dst, out, N);
    edge_kernel<<<(E2 + 7) / 8, 256>>>(ei, out, E, E2);
    norm_kernel<<<(N * 32 + 255) / 256, 256>>>(bias, out, N);
}

// round 6
// speedup vs baseline: 1.7457x; 1.7428x over previous
#include <cuda_runtime.h>

// Problem constants (N=100000, DIM=128, HEADS=4, C=32, E=1600000)
#define NMAX 100000
#define EMAX 1600000
#define DIMK 128

// Scratch (static __device__ — allocation-free per harness rules)
__device__ float g_xp[NMAX * DIMK];   // x @ W, [N,128]  (51.2 MB)
__device__ float g_asrc[NMAX * 4];    // [N,H]
__device__ float g_adst[NMAX * 4];    // [N,H]
__device__ int   g_cnt[NMAX];         // in-degree (excl self loop)
__device__ int   g_off[NMAX];         // CSR offsets
__device__ int   g_cur[NMAX];         // scatter cursors
__device__ int   g_bucket[EMAX];      // CSR adjacency: src per slot
__device__ int   g_total;

// ---------------------------------------------------------------------------
// Kernel A: zero counts + total
// ---------------------------------------------------------------------------
__global__ void zero_kernel(int N) {
    const int i = blockIdx.x * blockDim.x + threadIdx.x;
    if (i < N) g_cnt[i] = 0;
    if (i == 0) g_total = 0;
}

// ---------------------------------------------------------------------------
// Kernel B: histogram of dst (int atomics, spread addresses -> REDG-fast)
// ---------------------------------------------------------------------------
__global__ void hist_kernel(const int* __restrict__ ei, int E) {
    const int e = blockIdx.x * blockDim.x + threadIdx.x;
    if (e < E) atomicAdd(&g_cnt[ei[E + e]], 1);
}

// ---------------------------------------------------------------------------
// Kernel C: per-block scan + atomic base allocation (CSR offsets; order of
// blocks irrelevant — only contiguity per node matters)
// ---------------------------------------------------------------------------
__global__ void __launch_bounds__(1024) alloc_kernel(int N) {
    __shared__ int sdata[1024];
    __shared__ int sbase;
    const int i = blockIdx.x * 1024 + threadIdx.x;
    const int c = (i < N) ? g_cnt[i] : 0;
    sdata[threadIdx.x] = c;
    __syncthreads();
#pragma unroll
    for (int off = 1; off < 1024; off <<= 1) {
        int v = (threadIdx.x >= off) ? sdata[threadIdx.x - off] : 0;
        __syncthreads();
        sdata[threadIdx.x] += v;
        __syncthreads();
    }
    if (threadIdx.x == 1023) sbase = atomicAdd(&g_total, sdata[1023]);
    __syncthreads();
    const int excl = sdata[threadIdx.x] - c + sbase;
    if (i < N) { g_off[i] = excl; g_cur[i] = excl; }
}

// ---------------------------------------------------------------------------
// Kernel D: scatter edges into CSR buckets (store src only)
// ---------------------------------------------------------------------------
__global__ void scatter_kernel(const int* __restrict__ ei, int E) {
    const int e = blockIdx.x * blockDim.x + threadIdx.x;
    if (e >= E) return;
    const int src = ei[e];
    const int dst = ei[E + e];
    const int p = atomicAdd(&g_cur[dst], 1);
    g_bucket[p] = src;
}

// ---------------------------------------------------------------------------
// Kernel E: x_proj = x @ W (fp32 SIMT, 64-row tiles) + attention-coefficient
// epilogue: a_src/a_dst computed from live accumulators (saves a full re-read)
// ---------------------------------------------------------------------------
__global__ void __launch_bounds__(256) gemm_kernel(const float* __restrict__ x,
                                                   const float* __restrict__ W,
                                                   const float* __restrict__ att_src,
                                                   const float* __restrict__ att_dst,
                                                   int N) {
    __shared__ float sx[64][DIMK];
    const int block_row = blockIdx.x * 64;
    const int tid = threadIdx.x;
    const int nrows = min(64, N - block_row);

    const float4* x4 = (const float4*)(x + (size_t)block_row * DIMK);
    float4* sx4 = (float4*)&sx[0][0];
    for (int i = tid; i < nrows * 32; i += 256) sx4[i] = x4[i];
    __syncthreads();

    const int cg = tid & 31;   // col group: global cols 4cg..4cg+3 (head cg>>3)
    const int rg = tid >> 5;   // warp id: rows rg*8..rg*8+7

    float4 acc[8];
#pragma unroll
    for (int i = 0; i < 8; i++) acc[i] = make_float4(0.f, 0.f, 0.f, 0.f);

    const float4* W4 = (const float4*)W;
#pragma unroll 4
    for (int k = 0; k < DIMK; k++) {
        const float4 w = __ldg(&W4[k * 32 + cg]);
#pragma unroll
        for (int i = 0; i < 8; i++) {
            const float xv = sx[rg * 8 + i][k];
            acc[i].x = fmaf(xv, w.x, acc[i].x);
            acc[i].y = fmaf(xv, w.y, acc[i].y);
            acc[i].z = fmaf(xv, w.z, acc[i].z);
            acc[i].w = fmaf(xv, w.w, acc[i].w);
        }
    }

    // store x_proj
    float4* xp4 = (float4*)g_xp;
#pragma unroll
    for (int i = 0; i < 8; i++) {
        const int row = block_row + rg * 8 + i;
        if (row < N) xp4[row * 32 + cg] = acc[i];
    }

    // epilogue: a_src/a_dst (att flattened [H*C]=[128]; float4 idx == cg)
    const float4 as = __ldg(&((const float4*)att_src)[cg]);
    const float4 ad = __ldg(&((const float4*)att_dst)[cg]);
#pragma unroll
    for (int i = 0; i < 8; i++) {
        float ps = acc[i].x * as.x + acc[i].y * as.y + acc[i].z * as.z + acc[i].w * as.w;
        float pd = acc[i].x * ad.x + acc[i].y * ad.y + acc[i].z * ad.z + acc[i].w * ad.w;
#pragma unroll
        for (int off = 4; off >= 1; off >>= 1) {
            ps += __shfl_xor_sync(0xffffffffu, ps, off);
            pd += __shfl_xor_sync(0xffffffffu, pd, off);
        }
        const int row = block_row + rg * 8 + i;
        if ((cg & 7) == 0 && row < N) {
            const int h = cg >> 3;
            g_asrc[row * 4 + h] = ps;
            g_adst[row * 4 + h] = pd;
        }
    }
}

// ---------------------------------------------------------------------------
// Kernel F: aggregate. One warp per dst node; register accumulation (NO float
// atomics). Self loop handled inline. Softmax max-shift cancels -> use raw
// exp; normalize + bias + relu and write final out directly.
// ---------------------------------------------------------------------------
__global__ void __launch_bounds__(256) agg_kernel(const float* __restrict__ bias,
                                                  float* __restrict__ out, int N) {
    const int n = (blockIdx.x * blockDim.x + threadIdx.x) >> 5;
    const int lane = threadIdx.x & 31;
    if (n >= N) return;
    const int h = lane >> 3;

    const float4* xp4 = (const float4*)g_xp;
    const float adst_h = g_adst[n * 4 + h];

    // self loop
    float a = g_asrc[n * 4 + h] + adst_h;
    a = (a >= 0.f) ? a : 0.2f * a;
    float ex = __expf(a);
    float s = ex;
    float4 xv = xp4[n * 32 + lane];
    float4 acc = make_float4(ex * xv.x, ex * xv.y, ex * xv.z, ex * xv.w);

    const int beg = g_off[n];
    const int cnt = g_cnt[n];
    for (int base = 0; base < cnt; base += 32) {
        const int m = min(32, cnt - base);
        const int src_l = (lane < m) ? g_bucket[beg + base + lane] : 0;
        for (int j = 0; j < m; j++) {
            const int src = __shfl_sync(0xffffffffu, src_l, j);
            a = g_asrc[src * 4 + h] + adst_h;
            a = (a >= 0.f) ? a : 0.2f * a;
            ex = __expf(a);
            xv = xp4[src * 32 + lane];
            acc.x = fmaf(ex, xv.x, acc.x);
            acc.y = fmaf(ex, xv.y, acc.y);
            acc.z = fmaf(ex, xv.z, acc.z);
            acc.w = fmaf(ex, xv.w, acc.w);
            s += ex;
        }
    }

    const float inv = 1.f / (s + 1e-16f);
    const float4 b = __ldg(&((const float4*)bias)[lane]);
    float4 o;
    o.x = fmaxf(fmaf(acc.x, inv, b.x), 0.f);
    o.y = fmaxf(fmaf(acc.y, inv, b.y), 0.f);
    o.z = fmaxf(fmaf(acc.z, inv, b.z), 0.f);
    o.w = fmaxf(fmaf(acc.w, inv, b.w), 0.f);
    ((float4*)out)[n * 32 + lane] = o;
}

// ---------------------------------------------------------------------------
extern "C" void kernel_launch(void* const* d_in, const int* in_sizes, int n_in,
                              void* d_out, int out_size) {
    const float* x       = (const float*)d_in[0];
    const int* ei        = (const int*)d_in[1];   // int32 (JAX x64 disabled)
    const float* W       = (const float*)d_in[2];
    const float* att_src = (const float*)d_in[3];
    const float* att_dst = (const float*)d_in[4];
    const float* bias    = (const float*)d_in[5];
    float* out           = (float*)d_out;

    const int N = in_sizes[0] / DIMK;
    const int E = in_sizes[1] / 2;

    zero_kernel<<<(N + 255) / 256, 256>>>(N);
    hist_kernel<<<(E + 255) / 256, 256>>>(ei, E);
    alloc_kernel<<<(N + 1023) / 1024, 1024>>>(N);
    scatter_kernel<<<(E + 255) / 256, 256>>>(ei, E);
    gemm_kernel<<<(N + 63) / 64, 256>>>(x, W, att_src, att_dst, N);
    agg_kernel<<<(N * 32 + 255) / 256, 256>>>(bias, out, N);
}